// round 15
// baseline (speedup 1.0000x reference)
#include <cuda_runtime.h>

#define B_  64
#define T_  2048
#define H_  128
#define N3  384
#define BT  (B_ * T_)
#define NCHUNK  32
#define LAG     128
#define WAVES   (T_ + 2 * LAG)     // 2304
#define SCAN_CTAS 64
#define GEMM_CTAS 84
#define GRID      (SCAN_CTAS + GEMM_CTAS)   // 148, all resident
#define NT 256

typedef unsigned long long ull;

// Scratch (allocation-free rule): 3 gx buffers (3 layers alive), 3 activation
// buffers, flags.
__device__ float g_gx0[(size_t)BT * N3 + N3];
__device__ float g_gx1[(size_t)BT * N3 + N3];
__device__ float g_gx2[(size_t)BT * N3 + N3];
__device__ float g_bufA[(size_t)BT * H_];
__device__ float g_bufB[(size_t)BT * H_];
__device__ float g_bufC[(size_t)BT * H_];
__device__ int g_cnt[3][B_][NCHUNK];   // gx chunk counters (target 3 n-tiles)
__device__ int g_rdy[3][B_][NCHUNK];   // scan chunk-done flags

// ---------------- packed f32x2 helpers (register-only asm: safe) -----------
__device__ __forceinline__ ull pk2(float lo, float hi) {
    ull r; asm("mov.b64 %0,{%1,%2};" : "=l"(r) : "f"(lo), "f"(hi)); return r;
}
__device__ __forceinline__ ull ffma2(ull a, ull b, ull c) {
    ull d; asm("fma.rn.f32x2 %0,%1,%2,%3;" : "=l"(d) : "l"(a), "l"(b), "l"(c)); return d;
}
__device__ __forceinline__ float sum2(ull v) {
    float lo, hi; asm("mov.b64 {%0,%1},%2;" : "=f"(lo), "=f"(hi) : "l"(v));
    return lo + hi;
}
__device__ __forceinline__ void unpk2(ull v, float& lo, float& hi) {
    asm("mov.b64 {%0,%1},%2;" : "=f"(lo), "=f"(hi) : "l"(v));
}
__device__ __forceinline__ unsigned smem_u32(const void* p) {
    unsigned a;
    asm("{.reg .u64 u; cvta.to.shared.u64 u,%1; cvt.u32.u64 %0,u;}" : "=r"(a) : "l"(p));
    return a;
}
// Volatile explicit-shared ops: fast LDS/STS path, never hoisted across bars.
__device__ __forceinline__ void lds_v2u64(unsigned addr, ull& a, ull& b) {
    asm volatile("ld.shared.v2.u64 {%0,%1},[%2];" : "=l"(a), "=l"(b) : "r"(addr));
}
__device__ __forceinline__ void lds_u64(unsigned addr, ull& a) {
    asm volatile("ld.shared.u64 %0,[%1];" : "=l"(a) : "r"(addr));
}
__device__ __forceinline__ void sts_f32(unsigned addr, float v) {
    asm volatile("st.shared.f32 [%0],%1;" :: "r"(addr), "f"(v));
}
// Coherent L2 loads for intra-kernel-produced data (.cg skips L1 -> no staleness).
__device__ __forceinline__ float ldg_cg(const float* p) {
    float v; asm volatile("ld.global.cg.f32 %0,[%1];" : "=f"(v) : "l"(p)); return v;
}
__device__ __forceinline__ float4 ldg_cg4(const float* p) {
    float4 v;
    asm volatile("ld.global.cg.v4.f32 {%0,%1,%2,%3},[%4];"
                 : "=f"(v.x), "=f"(v.y), "=f"(v.z), "=f"(v.w) : "l"(p));
    return v;
}
// Acquire/release flag ops
__device__ __forceinline__ int ld_acq(const int* p) {
    int v; asm volatile("ld.acquire.gpu.global.b32 %0,[%1];" : "=r"(v) : "l"(p)); return v;
}
__device__ __forceinline__ void st_rel(int* p, int v) {
    asm volatile("st.release.gpu.global.b32 [%0],%1;" :: "l"(p), "r"(v) : "memory");
}
__device__ __forceinline__ void red_rel_add1(int* p) {
    asm volatile("red.release.gpu.global.add.s32 [%0],%1;" :: "l"(p), "r"(1) : "memory");
}

#define NLOG2E  (-1.442695040888963f)
#define N2LOG2E (-2.885390081777927f)

__device__ __forceinline__ float fsigmoid(float x) {
    float e = exp2f(fminf(x * NLOG2E, 126.f));
    return __fdividef(1.f, 1.f + e);
}

// R13 pair-split dot: dm = main column (z for even lanes / h for odd),
// dr = this lane's half of the r column.
__device__ __forceinline__ void dot_pair(unsigned rb, const ull* w2,
                                         unsigned roff, float& dm, float& dr) {
    ull aM0 = 0ULL, aM1 = 0ULL, aR = 0ULL;
    #pragma unroll
    for (int j = 0; j < 32; j++) {
        ull c0, c1, cr;
        lds_v2u64(rb + 16u * j, c0, c1);
        lds_u64(rb + 16u * j + roff, cr);
        aM0 = ffma2(c0, w2[2 * j    ], aM0);
        aM1 = ffma2(c1, w2[2 * j + 1], aM1);
        aR  = ffma2(cr, w2[64 + j   ], aR);
    }
    dm = sum2(aM0) + sum2(aM1);
    dr = sum2(aR);
}

// ---------------------------------------------------------------------------
// GEMM tile (proven): C[64,128] = A[64,128]@Bm + bias. 256 thr, uniform bars.
// ---------------------------------------------------------------------------
__device__ void gemm_tile(
    const float* A, const float* __restrict__ Bm,
    const float* __restrict__ bias, float* __restrict__ C,
    int N, int m0, int n0, int applySigmoid,
    float (*sA)[33], float (*sB)[128])
{
    const int tid = threadIdx.x;
    const int tx = tid & 15;
    const int ty = (tid >> 4) & 15;
    const int arow = (tid >> 3) & 31;
    const int akq  = tid & 7;
    const int brow = (tid >> 5) & 7;
    const int bcol = tid & 31;
    const unsigned sb_base = smem_u32(&sB[0][0]) + tx * 32;

    ull acc2[4][4];
    #pragma unroll
    for (int i = 0; i < 4; i++)
        #pragma unroll
        for (int j = 0; j < 4; j++) acc2[i][j] = 0ULL;

    for (int k0 = 0; k0 < 128; k0 += 32) {
        float4 a0, a1, b0, b1, b2, b3;
        a0 = ldg_cg4(A + (size_t)(m0 + arow     ) * H_ + k0 + akq * 4);
        a1 = ldg_cg4(A + (size_t)(m0 + arow + 32) * H_ + k0 + akq * 4);
        b0 = *(const float4*)(Bm + (size_t)(k0 + brow     ) * N + n0 + bcol * 4);
        b1 = *(const float4*)(Bm + (size_t)(k0 + brow +  8) * N + n0 + bcol * 4);
        b2 = *(const float4*)(Bm + (size_t)(k0 + brow + 16) * N + n0 + bcol * 4);
        b3 = *(const float4*)(Bm + (size_t)(k0 + brow + 24) * N + n0 + bcol * 4);
        __syncthreads();
        sA[arow     ][akq * 4 + 0] = a0.x;  sA[arow     ][akq * 4 + 1] = a0.y;
        sA[arow     ][akq * 4 + 2] = a0.z;  sA[arow     ][akq * 4 + 3] = a0.w;
        sA[arow + 32][akq * 4 + 0] = a1.x;  sA[arow + 32][akq * 4 + 1] = a1.y;
        sA[arow + 32][akq * 4 + 2] = a1.z;  sA[arow + 32][akq * 4 + 3] = a1.w;
        *(float4*)&sB[brow     ][bcol * 4] = b0;
        *(float4*)&sB[brow +  8][bcol * 4] = b1;
        *(float4*)&sB[brow + 16][bcol * 4] = b2;
        *(float4*)&sB[brow + 24][bcol * 4] = b3;
        __syncthreads();

        #pragma unroll
        for (int k = 0; k < 32; k++) {
            ull pa[4];
            #pragma unroll
            for (int i = 0; i < 4; i++) {
                float a = sA[ty * 4 + i][k];
                pa[i] = pk2(a, a);
            }
            ull b01, b23, b45, b67;
            lds_v2u64(sb_base + k * 512,      b01, b23);
            lds_v2u64(sb_base + k * 512 + 16, b45, b67);
            #pragma unroll
            for (int i = 0; i < 4; i++) {
                acc2[i][0] = ffma2(pa[i], b01, acc2[i][0]);
                acc2[i][1] = ffma2(pa[i], b23, acc2[i][1]);
                acc2[i][2] = ffma2(pa[i], b45, acc2[i][2]);
                acc2[i][3] = ffma2(pa[i], b67, acc2[i][3]);
            }
        }
    }

    float bs[8];
    #pragma unroll
    for (int j = 0; j < 8; j++) bs[j] = bias[n0 + tx * 8 + j];
    #pragma unroll
    for (int i = 0; i < 4; i++) {
        const int row = m0 + ty * 4 + i;
        float v[8];
        #pragma unroll
        for (int j = 0; j < 4; j++) unpk2(acc2[i][j], v[2 * j], v[2 * j + 1]);
        #pragma unroll
        for (int j = 0; j < 8; j++) {
            float x = v[j] + bs[j];
            v[j] = applySigmoid ? fsigmoid(x) : x;
        }
        float4 o0 = {v[0], v[1], v[2], v[3]};
        float4 o1 = {v[4], v[5], v[6], v[7]};
        *(float4*)(C + (size_t)row * N + n0 + tx * 8    ) = o0;
        *(float4*)(C + (size_t)row * N + n0 + tx * 8 + 4) = o1;
    }
}

__device__ __forceinline__ void wait_flag(const int* p, int target) {
    if (threadIdx.x == 0) {
        while (ld_acq(p) < target) __nanosleep(128);
    }
    __syncthreads();
}

__global__ void init_flags() {
    const int n = 3 * B_ * NCHUNK;
    int* a = &g_cnt[0][0][0];
    int* b = &g_rdy[0][0][0];
    for (int i = threadIdx.x; i < n; i += blockDim.x) { a[i] = 0; b[i] = 0; }
}

// ---------------------------------------------------------------------------
// Mega-kernel. Scan CTA: R13 pair-split step, 3 layers per wave (wavefront,
// layer l lags l*LAG), sharing the same w2[96] weight registers. One barrier
// per wave. GEMM workers: stripe-ordered merged list (deadlock-free: every
// item's wait depends only on strictly earlier items).
// ---------------------------------------------------------------------------
__global__ void __launch_bounds__(NT, 1) mega(
    const float* __restrict__ X,
    const float* __restrict__ kern,
    const float* __restrict__ rec,
    const float* __restrict__ b_in,
    const float* __restrict__ b_rec,
    const float* __restrict__ W_out,
    const float* __restrict__ b_out,
    float*       __restrict__ out)
{
    __shared__ __align__(16) float hbuf[6][H_];   // [layer*2+parity][unit]
    __shared__ float sA[64][33];
    __shared__ __align__(16) float sB[32][128];

    const int cta = blockIdx.x;
    const int t   = threadIdx.x;

    if (cta < SCAN_CTAS) {
        const int b    = cta;
        const int lane = t & 31;
        const int odd  = lane & 1;
        const int u    = (t >> 5) * 16 + (lane >> 1);   // hidden unit 0..127
        const int mcol = odd ? (256 + u) : u;           // main column (h / z)
        const int rcol = 128 + u;

        ull w2[96];
        #pragma unroll
        for (int j = 0; j < 64; j++)
            w2[j] = pk2(rec[(2 * j) * N3 + mcol], rec[(2 * j + 1) * N3 + mcol]);
        #pragma unroll
        for (int j = 0; j < 32; j++) {
            const int k0 = 4 * j + 2 * odd;
            w2[64 + j] = pk2(rec[k0 * N3 + rcol], rec[(k0 + 1) * N3 + rcol]);
        }
        const float bm  = b_rec[mcol];
        const float brr = b_rec[rcol];

        const unsigned hb   = smem_u32(&hbuf[0][0]);
        const unsigned roff = 8u * (unsigned)odd;
        const int rdel = rcol - mcol;                   // +128 (even) / -128 (odd)
        const size_t gbase = (size_t)b * T_ * N3 + mcol;
        const size_t ybase = (size_t)b * T_ * H_ + u;

        if (t < H_) {
            #pragma unroll
            for (int p = 0; p < 6; p++) hbuf[p][t] = 0.f;
        }
        float h0 = 0.f, h1 = 0.f, h2 = 0.f;
        int par = 0;

        for (int v = 0; v < WAVES; ++v) {
            const int s0 = v, s1 = v - LAG, s2 = v - 2 * LAG;
            const bool a0 = s0 < T_;
            const bool a1 = ((unsigned)s1) < (unsigned)T_;
            const bool a2 = ((unsigned)s2) < (unsigned)T_;

            if ((v & 63) == 0) {   // chunk boundary (all active layers aligned)
                if (t == 0) {
                    if (a0) while (ld_acq(&g_cnt[0][b][s0 >> 6]) < 3) __nanosleep(64);
                    if (a1) while (ld_acq(&g_cnt[1][b][s1 >> 6]) < 3) __nanosleep(64);
                    if (a2) while (ld_acq(&g_cnt[2][b][s2 >> 6]) < 3) __nanosleep(64);
                }
                __syncthreads();   // also orders h-init before first dot
            }

            // ---- layer 0 ----
            if (a0) {
                const float* gp = g_gx0 + gbase + (size_t)s0 * N3;
                float g0 = ldg_cg(gp), g1 = ldg_cg(gp + rdel);
                float dm, dr;
                dot_pair(hb + (unsigned)(0 + par) * 512u, w2, roff, dm, dr);
                float drO = __shfl_xor_sync(0xffffffffu, dr, 1);
                float pre = g0 + dm + bm;
                float sig = fsigmoid(pre);
                float zv  = __shfl_xor_sync(0xffffffffu, sig, 1);
                if (odd) {
                    float r    = fsigmoid(dr + drO + g1 + brr);
                    float arg  = fminf(fmaf(r, (dm + bm) * N2LOG2E, g0 * N2LOG2E), 126.f);
                    float cand = __fdividef(2.f, 1.f + exp2f(arg)) - 1.f;
                    float hn   = fmaf(zv, h0 - cand, cand);
                    h0 = hn;
                    sts_f32(hb + (unsigned)(0 + (1 - par)) * 512u + 4u * (unsigned)u, hn);
                    g_bufA[ybase + (size_t)s0 * H_] = hn;
                }
            }
            // ---- layer 1 ----
            if (a1) {
                const float* gp = g_gx1 + gbase + (size_t)s1 * N3;
                float g0 = ldg_cg(gp), g1 = ldg_cg(gp + rdel);
                float dm, dr;
                dot_pair(hb + (unsigned)(2 + par) * 512u, w2, roff, dm, dr);
                float drO = __shfl_xor_sync(0xffffffffu, dr, 1);
                float pre = g0 + dm + bm;
                float sig = fsigmoid(pre);
                float zv  = __shfl_xor_sync(0xffffffffu, sig, 1);
                if (odd) {
                    float r    = fsigmoid(dr + drO + g1 + brr);
                    float arg  = fminf(fmaf(r, (dm + bm) * N2LOG2E, g0 * N2LOG2E), 126.f);
                    float cand = __fdividef(2.f, 1.f + exp2f(arg)) - 1.f;
                    float hn   = fmaf(zv, h1 - cand, cand);
                    h1 = hn;
                    sts_f32(hb + (unsigned)(2 + (1 - par)) * 512u + 4u * (unsigned)u, hn);
                    g_bufB[ybase + (size_t)s1 * H_] = hn;
                }
            }
            // ---- layer 2 ----
            if (a2) {
                const float* gp = g_gx2 + gbase + (size_t)s2 * N3;
                float g0 = ldg_cg(gp), g1 = ldg_cg(gp + rdel);
                float dm, dr;
                dot_pair(hb + (unsigned)(4 + par) * 512u, w2, roff, dm, dr);
                float drO = __shfl_xor_sync(0xffffffffu, dr, 1);
                float pre = g0 + dm + bm;
                float sig = fsigmoid(pre);
                float zv  = __shfl_xor_sync(0xffffffffu, sig, 1);
                if (odd) {
                    float r    = fsigmoid(dr + drO + g1 + brr);
                    float arg  = fminf(fmaf(r, (dm + bm) * N2LOG2E, g0 * N2LOG2E), 126.f);
                    float cand = __fdividef(2.f, 1.f + exp2f(arg)) - 1.f;
                    float hn   = fmaf(zv, h2 - cand, cand);
                    h2 = hn;
                    sts_f32(hb + (unsigned)(4 + (1 - par)) * 512u + 4u * (unsigned)u, hn);
                    g_bufC[ybase + (size_t)s2 * H_] = hn;
                }
            }
            __syncthreads();       // new h visible; old parity free
            par ^= 1;

            if ((v & 63) == 63) {  // publish finished chunks
                __threadfence();
                __syncthreads();
                if (t == 0) {
                    if (a0) st_rel(&g_rdy[0][b][s0 >> 6], 1);
                    if (a1) st_rel(&g_rdy[1][b][s1 >> 6], 1);
                    if (a2) st_rel(&g_rdy[2][b][s2 >> 6], 1);
                }
            }
        }
    } else {
        // ================= GEMM worker (stripe scheme) =====================
        const int wrk = cta - SCAN_CTAS;

        // Merged dependency-ordered gx list: block c holds gx0[c], gx1[c-2],
        // gx2[c-4] (192 tiles each). Stripe order is deadlock-free.
        const int NBLK = NCHUNK + 4;           // 36
        for (int idx = wrk; idx < NBLK * 576; idx += GEMM_CTAS) {
            const int blk = idx / 576;
            const int sub = idx % 576;
            const int l   = sub / 192;
            const int r   = sub % 192;
            const int c   = blk - 2 * l;
            if (c < 0 || c >= NCHUNK) continue;
            const int b = r / 3;
            const int n = r % 3;
            const float* Asrc = (l == 0) ? X : ((l == 1) ? g_bufA : g_bufB);
            float* dst = (l == 0) ? g_gx0 : ((l == 1) ? g_gx1 : g_gx2);
            if (l > 0) wait_flag(&g_rdy[l - 1][b][c], 1);
            gemm_tile(Asrc, kern, b_in, dst, N3,
                      b * T_ + c * 64, n * 128, 0, sA, sB);
            __threadfence();
            __syncthreads();
            if (t == 0) red_rel_add1(&g_cnt[l][b][c]);
        }
        // Output projection + sigmoid (consumes g_bufC), chunk-ordered.
        for (int idx = wrk; idx < NCHUNK * B_; idx += GEMM_CTAS) {
            const int c = idx / B_;
            const int b = idx % B_;
            wait_flag(&g_rdy[2][b][c], 1);
            gemm_tile(g_bufC, W_out, b_out, out, H_,
                      b * T_ + c * 64, 0, 1, sA, sB);
        }
    }
}

// ---------------------------------------------------------------------------
extern "C" void kernel_launch(void* const* d_in, const int* in_sizes, int n_in,
                              void* d_out, int out_size)
{
    const float* X     = (const float*)d_in[0];
    const float* kern  = (const float*)d_in[1];
    const float* rec   = (const float*)d_in[2];
    const float* b_in  = (const float*)d_in[3];
    const float* b_rec = (const float*)d_in[4];
    const float* W_out = (const float*)d_in[5];
    const float* b_out = (const float*)d_in[6];
    float* out = (float*)d_out;

    init_flags<<<1, 256>>>();
    mega<<<GRID, NT>>>(X, kern, rec, b_in, b_rec, W_out, b_out, out);
}

// round 16
// speedup vs baseline: 1.4189x; 1.4189x over previous
#include <cuda_runtime.h>

#define B_  64
#define T_  2048
#define H_  128
#define N3  384
#define BT  (B_ * T_)
#define NCHUNK  32
#define LAG     192                // 3 chunks; preserves 65-wave producer slack
#define WAVES   (T_ + 2 * LAG)     // 2432
#define SCAN_CTAS 64
#define GEMM_CTAS 84
#define GRID      (SCAN_CTAS + GEMM_CTAS)   // 148, all resident
#define NT 256

typedef unsigned long long ull;

// Scratch (allocation-free rule): 3 gx buffers (3 layers alive), 3 activation
// buffers, flags. Each gx padded one row for the unconditional-ish prefetch.
__device__ float g_gx0[(size_t)BT * N3 + N3];
__device__ float g_gx1[(size_t)BT * N3 + N3];
__device__ float g_gx2[(size_t)BT * N3 + N3];
__device__ float g_bufA[(size_t)BT * H_];
__device__ float g_bufB[(size_t)BT * H_];
__device__ float g_bufC[(size_t)BT * H_];
__device__ int g_cnt[3][B_][NCHUNK];   // gx chunk counters (target 3 n-tiles)
__device__ int g_rdy[3][B_][NCHUNK];   // scan chunk-done flags

// ---------------- packed f32x2 helpers (register-only asm: safe) -----------
__device__ __forceinline__ ull pk2(float lo, float hi) {
    ull r; asm("mov.b64 %0,{%1,%2};" : "=l"(r) : "f"(lo), "f"(hi)); return r;
}
__device__ __forceinline__ ull ffma2(ull a, ull b, ull c) {
    ull d; asm("fma.rn.f32x2 %0,%1,%2,%3;" : "=l"(d) : "l"(a), "l"(b), "l"(c)); return d;
}
__device__ __forceinline__ float sum2(ull v) {
    float lo, hi; asm("mov.b64 {%0,%1},%2;" : "=f"(lo), "=f"(hi) : "l"(v));
    return lo + hi;
}
__device__ __forceinline__ void unpk2(ull v, float& lo, float& hi) {
    asm("mov.b64 {%0,%1},%2;" : "=f"(lo), "=f"(hi) : "l"(v));
}
__device__ __forceinline__ unsigned smem_u32(const void* p) {
    unsigned a;
    asm("{.reg .u64 u; cvta.to.shared.u64 u,%1; cvt.u32.u64 %0,u;}" : "=r"(a) : "l"(p));
    return a;
}
// Volatile explicit-shared ops: fast LDS/STS path, never hoisted across bars.
__device__ __forceinline__ void lds_v2u64(unsigned addr, ull& a, ull& b) {
    asm volatile("ld.shared.v2.u64 {%0,%1},[%2];" : "=l"(a), "=l"(b) : "r"(addr));
}
__device__ __forceinline__ void lds_u64(unsigned addr, ull& a) {
    asm volatile("ld.shared.u64 %0,[%1];" : "=l"(a) : "r"(addr));
}
__device__ __forceinline__ void sts_f32(unsigned addr, float v) {
    asm volatile("st.shared.f32 [%0],%1;" :: "r"(addr), "f"(v));
}
// Coherent L2 loads for intra-kernel-produced data (.cg skips L1 -> no staleness).
__device__ __forceinline__ float ldg_cg(const float* p) {
    float v; asm volatile("ld.global.cg.f32 %0,[%1];" : "=f"(v) : "l"(p)); return v;
}
__device__ __forceinline__ float4 ldg_cg4(const float* p) {
    float4 v;
    asm volatile("ld.global.cg.v4.f32 {%0,%1,%2,%3},[%4];"
                 : "=f"(v.x), "=f"(v.y), "=f"(v.z), "=f"(v.w) : "l"(p));
    return v;
}
// Acquire/release flag ops
__device__ __forceinline__ int ld_acq(const int* p) {
    int v; asm volatile("ld.acquire.gpu.global.b32 %0,[%1];" : "=r"(v) : "l"(p)); return v;
}
__device__ __forceinline__ void st_rel(int* p, int v) {
    asm volatile("st.release.gpu.global.b32 [%0],%1;" :: "l"(p), "r"(v) : "memory");
}
__device__ __forceinline__ void red_rel_add1(int* p) {
    asm volatile("red.release.gpu.global.add.s32 [%0],%1;" :: "l"(p), "r"(1) : "memory");
}

#define NLOG2E  (-1.442695040888963f)
#define N2LOG2E (-2.885390081777927f)

__device__ __forceinline__ float fsigmoid(float x) {
    float e = exp2f(fminf(x * NLOG2E, 126.f));
    return __fdividef(1.f, 1.f + e);
}

// Pair-split dot: dm = main column (z for even lanes / h for odd),
// dr = this lane's half of the r column.
__device__ __forceinline__ void dot_pair(unsigned rb, const ull* w2,
                                         unsigned roff, float& dm, float& dr) {
    ull aM0 = 0ULL, aM1 = 0ULL, aR = 0ULL;
    #pragma unroll
    for (int j = 0; j < 32; j++) {
        ull c0, c1, cr;
        lds_v2u64(rb + 16u * j, c0, c1);
        lds_u64(rb + 16u * j + roff, cr);
        aM0 = ffma2(c0, w2[2 * j    ], aM0);
        aM1 = ffma2(c1, w2[2 * j + 1], aM1);
        aR  = ffma2(cr, w2[64 + j   ], aR);
    }
    dm = sum2(aM0) + sum2(aM1);
    dr = sum2(aR);
}

// ---------------------------------------------------------------------------
// GEMM tile (proven): C[64,128] = A[64,128]@Bm + bias. 256 thr, uniform bars.
// ---------------------------------------------------------------------------
__device__ void gemm_tile(
    const float* A, const float* __restrict__ Bm,
    const float* __restrict__ bias, float* __restrict__ C,
    int N, int m0, int n0, int applySigmoid,
    float (*sA)[33], float (*sB)[128])
{
    const int tid = threadIdx.x;
    const int tx = tid & 15;
    const int ty = (tid >> 4) & 15;
    const int arow = (tid >> 3) & 31;
    const int akq  = tid & 7;
    const int brow = (tid >> 5) & 7;
    const int bcol = tid & 31;
    const unsigned sb_base = smem_u32(&sB[0][0]) + tx * 32;

    ull acc2[4][4];
    #pragma unroll
    for (int i = 0; i < 4; i++)
        #pragma unroll
        for (int j = 0; j < 4; j++) acc2[i][j] = 0ULL;

    for (int k0 = 0; k0 < 128; k0 += 32) {
        float4 a0, a1, b0, b1, b2, b3;
        a0 = ldg_cg4(A + (size_t)(m0 + arow     ) * H_ + k0 + akq * 4);
        a1 = ldg_cg4(A + (size_t)(m0 + arow + 32) * H_ + k0 + akq * 4);
        b0 = *(const float4*)(Bm + (size_t)(k0 + brow     ) * N + n0 + bcol * 4);
        b1 = *(const float4*)(Bm + (size_t)(k0 + brow +  8) * N + n0 + bcol * 4);
        b2 = *(const float4*)(Bm + (size_t)(k0 + brow + 16) * N + n0 + bcol * 4);
        b3 = *(const float4*)(Bm + (size_t)(k0 + brow + 24) * N + n0 + bcol * 4);
        __syncthreads();
        sA[arow     ][akq * 4 + 0] = a0.x;  sA[arow     ][akq * 4 + 1] = a0.y;
        sA[arow     ][akq * 4 + 2] = a0.z;  sA[arow     ][akq * 4 + 3] = a0.w;
        sA[arow + 32][akq * 4 + 0] = a1.x;  sA[arow + 32][akq * 4 + 1] = a1.y;
        sA[arow + 32][akq * 4 + 2] = a1.z;  sA[arow + 32][akq * 4 + 3] = a1.w;
        *(float4*)&sB[brow     ][bcol * 4] = b0;
        *(float4*)&sB[brow +  8][bcol * 4] = b1;
        *(float4*)&sB[brow + 16][bcol * 4] = b2;
        *(float4*)&sB[brow + 24][bcol * 4] = b3;
        __syncthreads();

        #pragma unroll
        for (int k = 0; k < 32; k++) {
            ull pa[4];
            #pragma unroll
            for (int i = 0; i < 4; i++) {
                float a = sA[ty * 4 + i][k];
                pa[i] = pk2(a, a);
            }
            ull b01, b23, b45, b67;
            lds_v2u64(sb_base + k * 512,      b01, b23);
            lds_v2u64(sb_base + k * 512 + 16, b45, b67);
            #pragma unroll
            for (int i = 0; i < 4; i++) {
                acc2[i][0] = ffma2(pa[i], b01, acc2[i][0]);
                acc2[i][1] = ffma2(pa[i], b23, acc2[i][1]);
                acc2[i][2] = ffma2(pa[i], b45, acc2[i][2]);
                acc2[i][3] = ffma2(pa[i], b67, acc2[i][3]);
            }
        }
    }

    float bs[8];
    #pragma unroll
    for (int j = 0; j < 8; j++) bs[j] = bias[n0 + tx * 8 + j];
    #pragma unroll
    for (int i = 0; i < 4; i++) {
        const int row = m0 + ty * 4 + i;
        float v[8];
        #pragma unroll
        for (int j = 0; j < 4; j++) unpk2(acc2[i][j], v[2 * j], v[2 * j + 1]);
        #pragma unroll
        for (int j = 0; j < 8; j++) {
            float x = v[j] + bs[j];
            v[j] = applySigmoid ? fsigmoid(x) : x;
        }
        float4 o0 = {v[0], v[1], v[2], v[3]};
        float4 o1 = {v[4], v[5], v[6], v[7]};
        *(float4*)(C + (size_t)row * N + n0 + tx * 8    ) = o0;
        *(float4*)(C + (size_t)row * N + n0 + tx * 8 + 4) = o1;
    }
}

__device__ __forceinline__ void wait_flag(const int* p, int target) {
    if (threadIdx.x == 0) {
        while (ld_acq(p) < target) __nanosleep(128);
    }
    __syncthreads();
}

__global__ void init_flags() {
    const int n = 3 * B_ * NCHUNK;
    int* a = &g_cnt[0][0][0];
    int* b = &g_rdy[0][0][0];
    for (int i = threadIdx.x; i < n; i += blockDim.x) { a[i] = 0; b[i] = 0; }
}

// ---------------------------------------------------------------------------
// Mega-kernel. Scan CTA: pair-split step, 3 layers per wave (wavefront,
// layer l lags l*LAG), shared w2[96], gx PREFETCHED ONE WAVE AHEAD per layer.
// Boundary waits cover chunk c and c+1 (prefetch crosses chunk edge).
// ---------------------------------------------------------------------------
__global__ void __launch_bounds__(NT, 1) mega(
    const float* __restrict__ X,
    const float* __restrict__ kern,
    const float* __restrict__ rec,
    const float* __restrict__ b_in,
    const float* __restrict__ b_rec,
    const float* __restrict__ W_out,
    const float* __restrict__ b_out,
    float*       __restrict__ out)
{
    __shared__ __align__(16) float hbuf[6][H_];   // [layer*2+parity][unit]
    __shared__ float sA[64][33];
    __shared__ __align__(16) float sB[32][128];

    const int cta = blockIdx.x;
    const int t   = threadIdx.x;

    if (cta < SCAN_CTAS) {
        const int b    = cta;
        const int lane = t & 31;
        const int odd  = lane & 1;
        const int u    = (t >> 5) * 16 + (lane >> 1);   // hidden unit 0..127
        const int mcol = odd ? (256 + u) : u;           // main column (h / z)
        const int rcol = 128 + u;

        ull w2[96];
        #pragma unroll
        for (int j = 0; j < 64; j++)
            w2[j] = pk2(rec[(2 * j) * N3 + mcol], rec[(2 * j + 1) * N3 + mcol]);
        #pragma unroll
        for (int j = 0; j < 32; j++) {
            const int k0 = 4 * j + 2 * odd;
            w2[64 + j] = pk2(rec[k0 * N3 + rcol], rec[(k0 + 1) * N3 + rcol]);
        }
        const float bm  = b_rec[mcol];
        const float brr = b_rec[rcol];

        const unsigned hb   = smem_u32(&hbuf[0][0]);
        const unsigned roff = 8u * (unsigned)odd;
        const int rdel = rcol - mcol;                   // +128 (even) / -128 (odd)
        const size_t gbase = (size_t)b * T_ * N3 + mcol;
        const size_t ybase = (size_t)b * T_ * H_ + u;
        const float* gx0p = g_gx0 + gbase;
        const float* gx1p = g_gx1 + gbase;
        const float* gx2p = g_gx2 + gbase;

        if (t < H_) {
            #pragma unroll
            for (int p = 0; p < 6; p++) hbuf[p][t] = 0.f;
        }
        float h0 = 0.f, h1 = 0.f, h2 = 0.f;
        // current-wave gx values (prefetched one wave ahead)
        float c00 = 0.f, c01 = 0.f, c10 = 0.f, c11 = 0.f, c20 = 0.f, c21 = 0.f;
        int par = 0;

        for (int v = 0; v < WAVES; ++v) {
            const int s0 = v, s1 = v - LAG, s2 = v - 2 * LAG;
            const bool a0 = s0 < T_;
            const bool a1 = ((unsigned)s1) < (unsigned)T_;
            const bool a2 = ((unsigned)s2) < (unsigned)T_;

            if ((v & 63) == 0) {   // chunk boundary (all active layers aligned)
                if (t == 0) {
                    if (a0) {
                        const int c = s0 >> 6;
                        while (ld_acq(&g_cnt[0][b][c]) < 3) __nanosleep(64);
                        if (c + 1 < NCHUNK)
                            while (ld_acq(&g_cnt[0][b][c + 1]) < 3) __nanosleep(64);
                    }
                    if (a1) {
                        const int c = s1 >> 6;
                        while (ld_acq(&g_cnt[1][b][c]) < 3) __nanosleep(64);
                        if (c + 1 < NCHUNK)
                            while (ld_acq(&g_cnt[1][b][c + 1]) < 3) __nanosleep(64);
                    }
                    if (a2) {
                        const int c = s2 >> 6;
                        while (ld_acq(&g_cnt[2][b][c]) < 3) __nanosleep(64);
                        if (c + 1 < NCHUNK)
                            while (ld_acq(&g_cnt[2][b][c + 1]) < 3) __nanosleep(64);
                    }
                }
                __syncthreads();   // also orders h-init before first dot
                // cold-start loads at layer activation
                if (s0 == 0) { c00 = ldg_cg(gx0p); c01 = ldg_cg(gx0p + rdel); }
                if (s1 == 0) { c10 = ldg_cg(gx1p); c11 = ldg_cg(gx1p + rdel); }
                if (s2 == 0) { c20 = ldg_cg(gx2p); c21 = ldg_cg(gx2p + rdel); }
            }

            // ---- layer 0 ----
            if (a0) {
                const float* gp = gx0p + (size_t)s0 * N3;
                const float g0 = c00, g1 = c01;
                if (s0 + 1 < T_) {          // prefetch next wave (covered by dot)
                    c00 = ldg_cg(gp + N3);
                    c01 = ldg_cg(gp + N3 + rdel);
                }
                float dm, dr;
                dot_pair(hb + (unsigned)(0 + par) * 512u, w2, roff, dm, dr);
                float drO = __shfl_xor_sync(0xffffffffu, dr, 1);
                float sig = fsigmoid(g0 + dm + bm);
                float zv  = __shfl_xor_sync(0xffffffffu, sig, 1);
                if (odd) {
                    float r    = fsigmoid(dr + drO + g1 + brr);
                    float arg  = fminf(fmaf(r, (dm + bm) * N2LOG2E, g0 * N2LOG2E), 126.f);
                    float cand = __fdividef(2.f, 1.f + exp2f(arg)) - 1.f;
                    float hn   = fmaf(zv, h0 - cand, cand);
                    h0 = hn;
                    sts_f32(hb + (unsigned)(0 + (1 - par)) * 512u + 4u * (unsigned)u, hn);
                    g_bufA[ybase + (size_t)s0 * H_] = hn;
                }
            }
            // ---- layer 1 ----
            if (a1) {
                const float* gp = gx1p + (size_t)s1 * N3;
                const float g0 = c10, g1 = c11;
                if (s1 + 1 < T_) {
                    c10 = ldg_cg(gp + N3);
                    c11 = ldg_cg(gp + N3 + rdel);
                }
                float dm, dr;
                dot_pair(hb + (unsigned)(2 + par) * 512u, w2, roff, dm, dr);
                float drO = __shfl_xor_sync(0xffffffffu, dr, 1);
                float sig = fsigmoid(g0 + dm + bm);
                float zv  = __shfl_xor_sync(0xffffffffu, sig, 1);
                if (odd) {
                    float r    = fsigmoid(dr + drO + g1 + brr);
                    float arg  = fminf(fmaf(r, (dm + bm) * N2LOG2E, g0 * N2LOG2E), 126.f);
                    float cand = __fdividef(2.f, 1.f + exp2f(arg)) - 1.f;
                    float hn   = fmaf(zv, h1 - cand, cand);
                    h1 = hn;
                    sts_f32(hb + (unsigned)(2 + (1 - par)) * 512u + 4u * (unsigned)u, hn);
                    g_bufB[ybase + (size_t)s1 * H_] = hn;
                }
            }
            // ---- layer 2 ----
            if (a2) {
                const float* gp = gx2p + (size_t)s2 * N3;
                const float g0 = c20, g1 = c21;
                if (s2 + 1 < T_) {
                    c20 = ldg_cg(gp + N3);
                    c21 = ldg_cg(gp + N3 + rdel);
                }
                float dm, dr;
                dot_pair(hb + (unsigned)(4 + par) * 512u, w2, roff, dm, dr);
                float drO = __shfl_xor_sync(0xffffffffu, dr, 1);
                float sig = fsigmoid(g0 + dm + bm);
                float zv  = __shfl_xor_sync(0xffffffffu, sig, 1);
                if (odd) {
                    float r    = fsigmoid(dr + drO + g1 + brr);
                    float arg  = fminf(fmaf(r, (dm + bm) * N2LOG2E, g0 * N2LOG2E), 126.f);
                    float cand = __fdividef(2.f, 1.f + exp2f(arg)) - 1.f;
                    float hn   = fmaf(zv, h2 - cand, cand);
                    h2 = hn;
                    sts_f32(hb + (unsigned)(4 + (1 - par)) * 512u + 4u * (unsigned)u, hn);
                    g_bufC[ybase + (size_t)s2 * H_] = hn;
                }
            }
            __syncthreads();       // new h visible; old parity free
            par ^= 1;

            if ((v & 63) == 63) {  // publish finished chunks
                __threadfence();
                __syncthreads();
                if (t == 0) {
                    if (a0) st_rel(&g_rdy[0][b][s0 >> 6], 1);
                    if (a1) st_rel(&g_rdy[1][b][s1 >> 6], 1);
                    if (a2) st_rel(&g_rdy[2][b][s2 >> 6], 1);
                }
            }
        }
    } else {
        // ================= GEMM worker (stripe scheme, LAG=3 chunks) =======
        const int wrk = cta - SCAN_CTAS;

        // Merged dependency-ordered gx list: block c holds gx0[c], gx1[c-3],
        // gx2[c-6] (192 tiles each). Stripe order is deadlock-free.
        const int NBLK = NCHUNK + 6;           // 38
        for (int idx = wrk; idx < NBLK * 576; idx += GEMM_CTAS) {
            const int blk = idx / 576;
            const int sub = idx % 576;
            const int l   = sub / 192;
            const int r   = sub % 192;
            const int c   = blk - 3 * l;
            if (c < 0 || c >= NCHUNK) continue;
            const int b = r / 3;
            const int n = r % 3;
            const float* Asrc = (l == 0) ? X : ((l == 1) ? g_bufA : g_bufB);
            float* dst = (l == 0) ? g_gx0 : ((l == 1) ? g_gx1 : g_gx2);
            if (l > 0) wait_flag(&g_rdy[l - 1][b][c], 1);
            gemm_tile(Asrc, kern, b_in, dst, N3,
                      b * T_ + c * 64, n * 128, 0, sA, sB);
            __threadfence();
            __syncthreads();
            if (t == 0) red_rel_add1(&g_cnt[l][b][c]);
        }
        // Output projection + sigmoid (consumes g_bufC), chunk-ordered.
        for (int idx = wrk; idx < NCHUNK * B_; idx += GEMM_CTAS) {
            const int c = idx / B_;
            const int b = idx % B_;
            wait_flag(&g_rdy[2][b][c], 1);
            gemm_tile(g_bufC, W_out, b_out, out, H_,
                      b * T_ + c * 64, 0, 1, sA, sB);
        }
    }
}

// ---------------------------------------------------------------------------
extern "C" void kernel_launch(void* const* d_in, const int* in_sizes, int n_in,
                              void* d_out, int out_size)
{
    const float* X     = (const float*)d_in[0];
    const float* kern  = (const float*)d_in[1];
    const float* rec   = (const float*)d_in[2];
    const float* b_in  = (const float*)d_in[3];
    const float* b_rec = (const float*)d_in[4];
    const float* W_out = (const float*)d_in[5];
    const float* b_out = (const float*)d_in[6];
    float* out = (float*)d_out;

    init_flags<<<1, 256>>>();
    mega<<<GRID, NT>>>(X, kern, rec, b_in, b_rec, W_out, b_out, out);
}